// round 8
// baseline (speedup 1.0000x reference)
#include <cuda_runtime.h>
#include <cstdint>

// Problem constants (fixed shapes from reference setup_inputs)
#define NB 4
#define NS 8192
#define NH 16
#define ND 64
#define NW 128
#define NC 64          // NS / NW
#define NTILES 6       // 3 neighbor chunks x 2 half-tiles of 64 keys
#define TK 64          // keys per tile
#define STR 68         // smem row stride (floats), 16B-aligned, padded vs bank conflicts

#define SMEM_FLOATS (128*STR + 64*STR + 64*STR + 128*STR + 128)
#define SMEM_BYTES  (SMEM_FLOATS * 4)

using ull = unsigned long long;

// ---- packed f32x2 helpers (FFMA2 path; see SASS_QUICKREF: only via PTX) ----
__device__ __forceinline__ ull dupf(float x) {
    ull r; asm("mov.b64 %0, {%1, %1};" : "=l"(r) : "f"(x)); return r;
}
__device__ __forceinline__ ull ffma2(ull a, ull b, ull c) {
    ull d; asm("fma.rn.f32x2 %0, %1, %2, %3;" : "=l"(d) : "l"(a), "l"(b), "l"(c)); return d;
}
__device__ __forceinline__ void unpack2(ull v, float& lo, float& hi) {
    asm("mov.b64 {%0, %1}, %2;" : "=f"(lo), "=f"(hi) : "l"(v));
}

// One CTA per (b, c, h). 256 threads.
// Thread micro-tile: rows x0..x0+3 (x0 = (tid>>3)*4), cols tc*8..tc*8+7 (tc = tid&7).
__global__ __launch_bounds__(256, 2)
void swa_no_overlap_kernel(const float* __restrict__ q,
                           const float* __restrict__ k,
                           const float* __restrict__ v,
                           float* __restrict__ outp,
                           float* __restrict__ attn)
{
    extern __shared__ float smem[];
    float* sQ   = smem;                    // [128][STR]  Q rows
    float* sKT  = smem + 128*STR;          // [64][STR]   K tile transposed: sKT[d][y]
    float* sV   = smem + 128*STR + 64*STR; // [64][STR]   V tile natural:    sV[y][d]
    float* sE   = smem + 128*STR + 128*STR;// [128][STR]  exp(S) tile:       sE[x][y]
    float* sRow = smem + 128*STR + 128*STR + 64*STR + 64*STR; // [128] rowsums

    const int tid = threadIdx.x;
    const int bid = blockIdx.x;
    const int h = bid & 15;
    const int c = (bid >> 4) & 63;
    const int b = bid >> 10;

    const int tr = tid >> 3;
    const int tc = tid & 7;
    const int x0 = tr << 2;

    const size_t qkvBase = (((size_t)b * NS + (size_t)c * NW) * NH + h) * ND;
    const float* gQ = q + qkvBase;
    float* gO = outp + qkvBase;
    float* gA = attn + (((size_t)b * NS + (size_t)c * NW) * NH + h) * 384;

    // ---- load Q chunk [128 x 64] into smem ----
    for (int f = tid; f < (NW * ND) / 4; f += 256) {      // 2048 float4
        int x  = f >> 4;
        int dq = (f & 15) << 2;
        float4 val = *(const float4*)(gQ + (size_t)x * (NH * ND) + dq);
        *(float4*)(sQ + x * STR + dq) = val;
    }
    if (tid < 128) sRow[tid] = 0.0f;

    // persistent PV accumulators: rows i (4), out-dim pairs j (4) -> cols tc*8+2j, +1
    ull oacc[4][4];
#pragma unroll
    for (int i = 0; i < 4; i++)
#pragma unroll
        for (int j = 0; j < 4; j++) oacc[i][j] = 0ull;

    for (int t = 0; t < NTILES; t++) {
        const int cn = c + (t >> 1) - 1;
        const bool valid = (cn >= 0) && (cn < NC);

        __syncthreads();   // previous tile fully consumed (sKT/sV/sE free)

        if (valid) {
            const size_t kvBase =
                (((size_t)b * NS + (size_t)cn * NW + (size_t)(t & 1) * TK) * NH + h) * ND;
            const float* gK = k + kvBase;
            const float* gV = v + kvBase;
            for (int f = tid; f < (TK * ND) / 4; f += 256) {   // 1024 float4
                int ky = f >> 4;
                int dq = (f & 15) << 2;
                float4 kv = *(const float4*)(gK + (size_t)ky * (NH * ND) + dq);
                // transpose K into sKT[d][y]
                sKT[(dq + 0) * STR + ky] = kv.x;
                sKT[(dq + 1) * STR + ky] = kv.y;
                sKT[(dq + 2) * STR + ky] = kv.z;
                sKT[(dq + 3) * STR + ky] = kv.w;
                float4 vv = *(const float4*)(gV + (size_t)ky * (NH * ND) + dq);
                *(float4*)(sV + ky * STR + dq) = vv;
            }
        }
        __syncthreads();   // tiles loaded

        if (valid) {
            // ---- QK: S[4 rows][8 cols] in f32x2 registers ----
            ull acc[4][4];
#pragma unroll
            for (int i = 0; i < 4; i++)
#pragma unroll
                for (int j = 0; j < 4; j++) acc[i][j] = 0ull;

            for (int d4 = 0; d4 < 16; d4++) {
                float qr[4][4];
#pragma unroll
                for (int i = 0; i < 4; i++) {
                    float4 qv = *(const float4*)(sQ + (x0 + i) * STR + (d4 << 2));
                    qr[i][0] = qv.x; qr[i][1] = qv.y; qr[i][2] = qv.z; qr[i][3] = qv.w;
                }
#pragma unroll
                for (int dd = 0; dd < 4; dd++) {
                    const ulonglong2* kp =
                        (const ulonglong2*)(sKT + ((d4 << 2) + dd) * STR + (tc << 3));
                    ulonglong2 ka = kp[0];
                    ulonglong2 kb = kp[1];
#pragma unroll
                    for (int i = 0; i < 4; i++) {
                        ull qd = dupf(qr[i][dd]);
                        acc[i][0] = ffma2(qd, ka.x, acc[i][0]);
                        acc[i][1] = ffma2(qd, ka.y, acc[i][1]);
                        acc[i][2] = ffma2(qd, kb.x, acc[i][2]);
                        acc[i][3] = ffma2(qd, kb.y, acc[i][3]);
                    }
                }
            }

            // ---- exp, write unnormalized E to global attn, stage into sE, rowsum ----
#pragma unroll
            for (int i = 0; i < 4; i++) {
                float e[8];
                unpack2(acc[i][0], e[0], e[1]);
                unpack2(acc[i][1], e[2], e[3]);
                unpack2(acc[i][2], e[4], e[5]);
                unpack2(acc[i][3], e[6], e[7]);
                float ssum = 0.0f;
#pragma unroll
                for (int j = 0; j < 8; j++) { e[j] = __expf(e[j]); ssum += e[j]; }
                float4 e0 = make_float4(e[0], e[1], e[2], e[3]);
                float4 e1 = make_float4(e[4], e[5], e[6], e[7]);
                float* ga = gA + (size_t)(x0 + i) * (NH * 384) + t * 64 + (tc << 3);
                *(float4*)ga       = e0;
                *(float4*)(ga + 4) = e1;
                *(float4*)(sE + (x0 + i) * STR + (tc << 3))     = e0;
                *(float4*)(sE + (x0 + i) * STR + (tc << 3) + 4) = e1;
                ssum += __shfl_xor_sync(0xffffffffu, ssum, 1);
                ssum += __shfl_xor_sync(0xffffffffu, ssum, 2);
                ssum += __shfl_xor_sync(0xffffffffu, ssum, 4);
                if (tc == 0) sRow[x0 + i] += ssum;   // row owned by exactly one 8-lane group
            }
        } else {
            // zero-padded neighbor: scores are exactly 0 -> exp = 1, V = 0 (no PV term)
            const float4 ones = make_float4(1.0f, 1.0f, 1.0f, 1.0f);
#pragma unroll
            for (int i = 0; i < 4; i++) {
                float* ga = gA + (size_t)(x0 + i) * (NH * 384) + t * 64 + (tc << 3);
                *(float4*)ga       = ones;
                *(float4*)(ga + 4) = ones;
                if (tc == 0) sRow[x0 + i] += 64.0f;
            }
        }
        __syncthreads();   // sE complete

        if (valid) {
            // ---- PV: O[4 rows][8 dims] += E[rows][y] * V[y][dims] ----
            for (int y4 = 0; y4 < 16; y4++) {
                float er[4][4];
#pragma unroll
                for (int i = 0; i < 4; i++) {
                    float4 ev = *(const float4*)(sE + (x0 + i) * STR + (y4 << 2));
                    er[i][0] = ev.x; er[i][1] = ev.y; er[i][2] = ev.z; er[i][3] = ev.w;
                }
#pragma unroll
                for (int dd = 0; dd < 4; dd++) {
                    const ulonglong2* vp =
                        (const ulonglong2*)(sV + ((y4 << 2) + dd) * STR + (tc << 3));
                    ulonglong2 va = vp[0];
                    ulonglong2 vb = vp[1];
#pragma unroll
                    for (int i = 0; i < 4; i++) {
                        ull ed = dupf(er[i][dd]);
                        oacc[i][0] = ffma2(ed, va.x, oacc[i][0]);
                        oacc[i][1] = ffma2(ed, va.y, oacc[i][1]);
                        oacc[i][2] = ffma2(ed, vb.x, oacc[i][2]);
                        oacc[i][3] = ffma2(ed, vb.y, oacc[i][3]);
                    }
                }
            }
        }
    }

    __syncthreads();                 // sRow final; all E global writes visible block-wide
    if (tid < 128) sRow[tid] = 1.0f / sRow[tid];
    __syncthreads();

    // ---- normalize O and write out ----
#pragma unroll
    for (int i = 0; i < 4; i++) {
        float inv = sRow[x0 + i];
        float o[8];
        unpack2(oacc[i][0], o[0], o[1]);
        unpack2(oacc[i][1], o[2], o[3]);
        unpack2(oacc[i][2], o[4], o[5]);
        unpack2(oacc[i][3], o[6], o[7]);
#pragma unroll
        for (int j = 0; j < 8; j++) o[j] *= inv;
        float* go = gO + (size_t)(x0 + i) * (NH * ND) + (tc << 3);
        *(float4*)go       = make_float4(o[0], o[1], o[2], o[3]);
        *(float4*)(go + 4) = make_float4(o[4], o[5], o[6], o[7]);
    }

    // ---- normalize attn in-place (RMW; this CTA's 192KB block is L2-hot) ----
    for (int f = tid; f < (NW * 384) / 4; f += 256) {     // 12288 float4
        int row = f / 96;            // 96 float4 per row
        int col = (f % 96) << 2;
        float inv = sRow[row];
        float4* p = (float4*)(gA + (size_t)row * (NH * 384) + col);
        float4 val = *p;
        val.x *= inv; val.y *= inv; val.z *= inv; val.w *= inv;
        *p = val;
    }
}

extern "C" void kernel_launch(void* const* d_in, const int* in_sizes, int n_in,
                              void* d_out, int out_size)
{
    const float* q = (const float*)d_in[0];
    const float* k = (const float*)d_in[1];
    const float* v = (const float*)d_in[2];

    float* outp = (float*)d_out;
    // tuple output: out [4,8192,16,64] first, then attn [4,8192,16,384]
    float* attn = outp + (size_t)NB * NS * NH * ND;

    cudaFuncSetAttribute(swa_no_overlap_kernel,
                         cudaFuncAttributeMaxDynamicSharedMemorySize, SMEM_BYTES);
    swa_no_overlap_kernel<<<NB * NC * NH, 256, SMEM_BYTES>>>(q, k, v, outp, attn);
}

// round 12
// speedup vs baseline: 1.0001x; 1.0001x over previous
#include <cuda_runtime.h>
#include <cstdint>

// Problem constants (fixed shapes from reference setup_inputs)
#define NB 4
#define NS 8192
#define NH 16
#define ND 64
#define NW 128
#define NC 64          // NS / NW
#define NTILES 6       // 3 neighbor chunks x 2 half-tiles of 64 keys
#define TK 64          // keys per tile
#define STR 68         // smem row stride (floats), 16B-aligned, padded vs bank conflicts

#define SMEM_FLOATS (128*STR + 64*STR + 64*STR + 128*STR + 128)
#define SMEM_BYTES  (SMEM_FLOATS * 4)

using ull = unsigned long long;

// ---- packed f32x2 helpers (FFMA2 path; see SASS_QUICKREF: only via PTX) ----
__device__ __forceinline__ ull dupf(float x) {
    ull r; asm("mov.b64 %0, {%1, %1};" : "=l"(r) : "f"(x)); return r;
}
__device__ __forceinline__ ull ffma2(ull a, ull b, ull c) {
    ull d; asm("fma.rn.f32x2 %0, %1, %2, %3;" : "=l"(d) : "l"(a), "l"(b), "l"(c)); return d;
}
__device__ __forceinline__ void unpack2(ull v, float& lo, float& hi) {
    asm("mov.b64 {%0, %1}, %2;" : "=f"(lo), "=f"(hi) : "l"(v));
}

// One CTA per (b, c, h). 256 threads.
// Thread micro-tile: rows x0..x0+3 (x0 = (tid>>3)*4), cols tc*8..tc*8+7 (tc = tid&7).
__global__ __launch_bounds__(256, 2)
void swa_no_overlap_kernel(const float* __restrict__ q,
                           const float* __restrict__ k,
                           const float* __restrict__ v,
                           float* __restrict__ outp,
                           float* __restrict__ attn)
{
    extern __shared__ float smem[];
    float* sQ   = smem;                    // [128][STR]  Q rows
    float* sKT  = smem + 128*STR;          // [64][STR]   K tile transposed: sKT[d][y]
    float* sV   = smem + 128*STR + 64*STR; // [64][STR]   V tile natural:    sV[y][d]
    float* sE   = smem + 128*STR + 128*STR;// [128][STR]  exp(S) tile:       sE[x][y]
    float* sRow = smem + 128*STR + 128*STR + 64*STR + 64*STR; // [128] rowsums

    const int tid = threadIdx.x;
    const int bid = blockIdx.x;
    const int h = bid & 15;
    const int c = (bid >> 4) & 63;
    const int b = bid >> 10;

    const int tr = tid >> 3;
    const int tc = tid & 7;
    const int x0 = tr << 2;

    const size_t qkvBase = (((size_t)b * NS + (size_t)c * NW) * NH + h) * ND;
    const float* gQ = q + qkvBase;
    float* gO = outp + qkvBase;
    float* gA = attn + (((size_t)b * NS + (size_t)c * NW) * NH + h) * 384;

    // ---- load Q chunk [128 x 64] into smem ----
    for (int f = tid; f < (NW * ND) / 4; f += 256) {      // 2048 float4
        int x  = f >> 4;
        int dq = (f & 15) << 2;
        float4 val = *(const float4*)(gQ + (size_t)x * (NH * ND) + dq);
        *(float4*)(sQ + x * STR + dq) = val;
    }
    if (tid < 128) sRow[tid] = 0.0f;

    // persistent PV accumulators: rows i (4), out-dim pairs j (4) -> cols tc*8+2j, +1
    ull oacc[4][4];
#pragma unroll
    for (int i = 0; i < 4; i++)
#pragma unroll
        for (int j = 0; j < 4; j++) oacc[i][j] = 0ull;

    for (int t = 0; t < NTILES; t++) {
        const int cn = c + (t >> 1) - 1;
        const bool valid = (cn >= 0) && (cn < NC);

        __syncthreads();   // previous tile fully consumed (sKT/sV/sE free)

        if (valid) {
            const size_t kvBase =
                (((size_t)b * NS + (size_t)cn * NW + (size_t)(t & 1) * TK) * NH + h) * ND;
            const float* gK = k + kvBase;
            const float* gV = v + kvBase;
            for (int f = tid; f < (TK * ND) / 4; f += 256) {   // 1024 float4
                int ky = f >> 4;
                int dq = (f & 15) << 2;
                float4 kv = *(const float4*)(gK + (size_t)ky * (NH * ND) + dq);
                // transpose K into sKT[d][y]
                sKT[(dq + 0) * STR + ky] = kv.x;
                sKT[(dq + 1) * STR + ky] = kv.y;
                sKT[(dq + 2) * STR + ky] = kv.z;
                sKT[(dq + 3) * STR + ky] = kv.w;
                float4 vv = *(const float4*)(gV + (size_t)ky * (NH * ND) + dq);
                *(float4*)(sV + ky * STR + dq) = vv;
            }
        }
        __syncthreads();   // tiles loaded

        if (valid) {
            // ---- QK: S[4 rows][8 cols] in f32x2 registers ----
            ull acc[4][4];
#pragma unroll
            for (int i = 0; i < 4; i++)
#pragma unroll
                for (int j = 0; j < 4; j++) acc[i][j] = 0ull;

            for (int d4 = 0; d4 < 16; d4++) {
                float qr[4][4];
#pragma unroll
                for (int i = 0; i < 4; i++) {
                    float4 qv = *(const float4*)(sQ + (x0 + i) * STR + (d4 << 2));
                    qr[i][0] = qv.x; qr[i][1] = qv.y; qr[i][2] = qv.z; qr[i][3] = qv.w;
                }
#pragma unroll
                for (int dd = 0; dd < 4; dd++) {
                    const ulonglong2* kp =
                        (const ulonglong2*)(sKT + ((d4 << 2) + dd) * STR + (tc << 3));
                    ulonglong2 ka = kp[0];
                    ulonglong2 kb = kp[1];
#pragma unroll
                    for (int i = 0; i < 4; i++) {
                        ull qd = dupf(qr[i][dd]);
                        acc[i][0] = ffma2(qd, ka.x, acc[i][0]);
                        acc[i][1] = ffma2(qd, ka.y, acc[i][1]);
                        acc[i][2] = ffma2(qd, kb.x, acc[i][2]);
                        acc[i][3] = ffma2(qd, kb.y, acc[i][3]);
                    }
                }
            }

            // ---- exp, write unnormalized E to global attn, stage into sE, rowsum ----
#pragma unroll
            for (int i = 0; i < 4; i++) {
                float e[8];
                unpack2(acc[i][0], e[0], e[1]);
                unpack2(acc[i][1], e[2], e[3]);
                unpack2(acc[i][2], e[4], e[5]);
                unpack2(acc[i][3], e[6], e[7]);
                float ssum = 0.0f;
#pragma unroll
                for (int j = 0; j < 8; j++) { e[j] = __expf(e[j]); ssum += e[j]; }
                float4 e0 = make_float4(e[0], e[1], e[2], e[3]);
                float4 e1 = make_float4(e[4], e[5], e[6], e[7]);
                float* ga = gA + (size_t)(x0 + i) * (NH * 384) + t * 64 + (tc << 3);
                *(float4*)ga       = e0;
                *(float4*)(ga + 4) = e1;
                *(float4*)(sE + (x0 + i) * STR + (tc << 3))     = e0;
                *(float4*)(sE + (x0 + i) * STR + (tc << 3) + 4) = e1;
                ssum += __shfl_xor_sync(0xffffffffu, ssum, 1);
                ssum += __shfl_xor_sync(0xffffffffu, ssum, 2);
                ssum += __shfl_xor_sync(0xffffffffu, ssum, 4);
                if (tc == 0) sRow[x0 + i] += ssum;   // row owned by exactly one 8-lane group
            }
        } else {
            // zero-padded neighbor: scores are exactly 0 -> exp = 1, V = 0 (no PV term)
            const float4 ones = make_float4(1.0f, 1.0f, 1.0f, 1.0f);
#pragma unroll
            for (int i = 0; i < 4; i++) {
                float* ga = gA + (size_t)(x0 + i) * (NH * 384) + t * 64 + (tc << 3);
                *(float4*)ga       = ones;
                *(float4*)(ga + 4) = ones;
                if (tc == 0) sRow[x0 + i] += 64.0f;
            }
        }
        __syncthreads();   // sE complete

        if (valid) {
            // ---- PV: O[4 rows][8 dims] += E[rows][y] * V[y][dims] ----
            for (int y4 = 0; y4 < 16; y4++) {
                float er[4][4];
#pragma unroll
                for (int i = 0; i < 4; i++) {
                    float4 ev = *(const float4*)(sE + (x0 + i) * STR + (y4 << 2));
                    er[i][0] = ev.x; er[i][1] = ev.y; er[i][2] = ev.z; er[i][3] = ev.w;
                }
#pragma unroll
                for (int dd = 0; dd < 4; dd++) {
                    const ulonglong2* vp =
                        (const ulonglong2*)(sV + ((y4 << 2) + dd) * STR + (tc << 3));
                    ulonglong2 va = vp[0];
                    ulonglong2 vb = vp[1];
#pragma unroll
                    for (int i = 0; i < 4; i++) {
                        ull ed = dupf(er[i][dd]);
                        oacc[i][0] = ffma2(ed, va.x, oacc[i][0]);
                        oacc[i][1] = ffma2(ed, va.y, oacc[i][1]);
                        oacc[i][2] = ffma2(ed, vb.x, oacc[i][2]);
                        oacc[i][3] = ffma2(ed, vb.y, oacc[i][3]);
                    }
                }
            }
        }
    }

    __syncthreads();                 // sRow final; all E global writes visible block-wide
    if (tid < 128) sRow[tid] = 1.0f / sRow[tid];
    __syncthreads();

    // ---- normalize O and write out ----
#pragma unroll
    for (int i = 0; i < 4; i++) {
        float inv = sRow[x0 + i];
        float o[8];
        unpack2(oacc[i][0], o[0], o[1]);
        unpack2(oacc[i][1], o[2], o[3]);
        unpack2(oacc[i][2], o[4], o[5]);
        unpack2(oacc[i][3], o[6], o[7]);
#pragma unroll
        for (int j = 0; j < 8; j++) o[j] *= inv;
        float* go = gO + (size_t)(x0 + i) * (NH * ND) + (tc << 3);
        *(float4*)go       = make_float4(o[0], o[1], o[2], o[3]);
        *(float4*)(go + 4) = make_float4(o[4], o[5], o[6], o[7]);
    }

    // ---- normalize attn in-place (RMW; this CTA's 192KB block is L2-hot) ----
    for (int f = tid; f < (NW * 384) / 4; f += 256) {     // 12288 float4
        int row = f / 96;            // 96 float4 per row
        int col = (f % 96) << 2;
        float inv = sRow[row];
        float4* p = (float4*)(gA + (size_t)row * (NH * 384) + col);
        float4 val = *p;
        val.x *= inv; val.y *= inv; val.z *= inv; val.w *= inv;
        *p = val;
    }
}

extern "C" void kernel_launch(void* const* d_in, const int* in_sizes, int n_in,
                              void* d_out, int out_size)
{
    const float* q = (const float*)d_in[0];
    const float* k = (const float*)d_in[1];
    const float* v = (const float*)d_in[2];

    float* outp = (float*)d_out;
    // tuple output: out [4,8192,16,64] first, then attn [4,8192,16,384]
    float* attn = outp + (size_t)NB * NS * NH * ND;

    cudaFuncSetAttribute(swa_no_overlap_kernel,
                         cudaFuncAttributeMaxDynamicSharedMemorySize, SMEM_BYTES);
    swa_no_overlap_kernel<<<NB * NC * NH, 256, SMEM_BYTES>>>(q, k, v, outp, attn);
}